// round 1
// baseline (speedup 1.0000x reference)
#include <cuda_runtime.h>
#include <stdint.h>

#define N_NODES 50000
#define N_EDGES 800000
#define IN_C    128
#define HID_C   128
#define OUT_C   64

// ---------------- scratch (static device globals; no allocation) ------------
__device__ float g_deg [N_NODES];
__device__ float g_dinv[N_NODES];
__device__ float g_h1  [N_NODES * HID_C];   // pre-scaled GEMM1 output
__device__ float g_agg1[N_NODES * HID_C];   // layer-1 aggregation
__device__ float g_x2  [N_NODES * HID_C];   // relu(epilogue1) = layer-2 input
__device__ float g_h2  [N_NODES * OUT_C];
__device__ float g_agg2[N_NODES * OUT_C];

// ---------------- degree / dinv ---------------------------------------------
__global__ void k_deg_init() {
    int i = blockIdx.x * blockDim.x + threadIdx.x;
    if (i < N_NODES) g_deg[i] = 1.0f;          // self-loop
}

__global__ void k_deg_count(const int* __restrict__ dst) {
    int e = blockIdx.x * blockDim.x + threadIdx.x;
    if (e < N_EDGES) atomicAdd(&g_deg[dst[e]], 1.0f);
}

__global__ void k_dinv() {
    int i = blockIdx.x * blockDim.x + threadIdx.x;
    if (i < N_NODES) g_dinv[i] = rsqrtf(g_deg[i]);
}

// ---------------- GEMM: H = (X @ W) * dinv[row]; AGG = H (self-loop init) ---
// X: [N_NODES, 128] row-major, W: [128, COUT] row-major.
// Block computes BM=64 rows x COUT cols with 256 threads.
template <int COUT>
__global__ __launch_bounds__(256)
void k_gemm_scale(const float* __restrict__ X, const float* __restrict__ W,
                  float* __restrict__ H, float* __restrict__ AGG)
{
    constexpr int BM  = 64;
    constexpr int BK  = 32;
    constexpr int CQ  = COUT / 4;      // column quads per row: 32 (128) / 16 (64)
    constexpr int RT  = 256 / CQ;      // thread row-groups: 8 / 16
    constexpr int RPT = BM / RT;       // rows per thread: 8 / 4
    constexpr int SXW = BK + 4;        // pad keeps 16B alignment (36 floats = 144B)

    __shared__ float sX[BM][SXW];
    __shared__ float sW[BK][COUT];

    const int tid  = threadIdx.x;
    const int colq = tid % CQ;
    const int rgrp = tid / CQ;
    const int row0 = blockIdx.x * BM;

    float acc[RPT][4];
#pragma unroll
    for (int r = 0; r < RPT; r++) { acc[r][0]=acc[r][1]=acc[r][2]=acc[r][3]=0.f; }

    for (int k0 = 0; k0 < IN_C; k0 += BK) {
        // load X tile: 64 rows x 32 cols = 512 float4
#pragma unroll
        for (int i = tid; i < BM * BK / 4; i += 256) {
            int r = i / (BK / 4);
            int q = i % (BK / 4);
            int gr = row0 + r;
            float4 v = make_float4(0.f, 0.f, 0.f, 0.f);
            if (gr < N_NODES)
                v = *reinterpret_cast<const float4*>(X + (size_t)gr * IN_C + k0 + 4 * q);
            *reinterpret_cast<float4*>(&sX[r][4 * q]) = v;
        }
        // load W tile: rows k0..k0+BK contiguous in memory
        const float4* wsrc = reinterpret_cast<const float4*>(W + (size_t)k0 * COUT);
        float4* wdst = reinterpret_cast<float4*>(&sW[0][0]);
#pragma unroll
        for (int i = tid; i < BK * COUT / 4; i += 256)
            wdst[i] = wsrc[i];
        __syncthreads();

#pragma unroll
        for (int k = 0; k < BK; k++) {
            float4 w = *reinterpret_cast<const float4*>(&sW[k][4 * colq]);
#pragma unroll
            for (int r = 0; r < RPT; r++) {
                float xv = sX[rgrp * RPT + r][k];
                acc[r][0] = fmaf(xv, w.x, acc[r][0]);
                acc[r][1] = fmaf(xv, w.y, acc[r][1]);
                acc[r][2] = fmaf(xv, w.z, acc[r][2]);
                acc[r][3] = fmaf(xv, w.w, acc[r][3]);
            }
        }
        __syncthreads();
    }

#pragma unroll
    for (int r = 0; r < RPT; r++) {
        int gr = row0 + rgrp * RPT + r;
        if (gr < N_NODES) {
            float dv = g_dinv[gr];
            float4 o = make_float4(acc[r][0] * dv, acc[r][1] * dv,
                                   acc[r][2] * dv, acc[r][3] * dv);
            size_t off = (size_t)gr * COUT + 4 * colq;
            *reinterpret_cast<float4*>(H   + off) = o;
            *reinterpret_cast<float4*>(AGG + off) = o;   // self-loop contribution
        }
    }
}

// ---------------- edge scatter: AGG[dst] += H[src] ---------------------------
// LPE lanes per edge, one float4 per lane; vectorized global reduction.
template <int COUT>
__global__ __launch_bounds__(256)
void k_scatter(const int* __restrict__ src, const int* __restrict__ dst,
               const float* __restrict__ H, float* __restrict__ AGG)
{
    constexpr int LPE = COUT / 4;       // 32 (layer1) / 16 (layer2)
    int gt = blockIdx.x * blockDim.x + threadIdx.x;
    int e    = gt / LPE;
    int lane = gt % LPE;
    if (e >= N_EDGES) return;

    int s = __ldg(&src[e]);
    int d = __ldg(&dst[e]);

    float4 v = *reinterpret_cast<const float4*>(H + (size_t)s * COUT + 4 * lane);
    float* p = AGG + (size_t)d * COUT + 4 * lane;
    asm volatile("red.global.add.v4.f32 [%0], {%1, %2, %3, %4};"
                 :: "l"(p), "f"(v.x), "f"(v.y), "f"(v.z), "f"(v.w)
                 : "memory");
}

// ---------------- epilogue 1: x2 = relu(agg1 * dinv + b1) --------------------
__global__ void k_epi1(const float* __restrict__ b1) {
    int i = blockIdx.x * blockDim.x + threadIdx.x;
    constexpr int Q = HID_C / 4;
    if (i >= N_NODES * Q) return;
    int row = i / Q, cq = i % Q;
    float dv = g_dinv[row];
    float4 a = *reinterpret_cast<const float4*>(&g_agg1[(size_t)row * HID_C + 4 * cq]);
    float4 b = *reinterpret_cast<const float4*>(b1 + 4 * cq);
    float4 o;
    o.x = fmaxf(fmaf(a.x, dv, b.x), 0.f);
    o.y = fmaxf(fmaf(a.y, dv, b.y), 0.f);
    o.z = fmaxf(fmaf(a.z, dv, b.z), 0.f);
    o.w = fmaxf(fmaf(a.w, dv, b.w), 0.f);
    *reinterpret_cast<float4*>(&g_x2[(size_t)row * HID_C + 4 * cq]) = o;
}

// ---------------- epilogue 2: out = agg2 * dinv + b2 -------------------------
__global__ void k_epi2(const float* __restrict__ b2, float* __restrict__ out) {
    int i = blockIdx.x * blockDim.x + threadIdx.x;
    constexpr int Q = OUT_C / 4;
    if (i >= N_NODES * Q) return;
    int row = i / Q, cq = i % Q;
    float dv = g_dinv[row];
    float4 a = *reinterpret_cast<const float4*>(&g_agg2[(size_t)row * OUT_C + 4 * cq]);
    float4 b = *reinterpret_cast<const float4*>(b2 + 4 * cq);
    float4 o;
    o.x = fmaf(a.x, dv, b.x);
    o.y = fmaf(a.y, dv, b.y);
    o.z = fmaf(a.z, dv, b.z);
    o.w = fmaf(a.w, dv, b.w);
    *reinterpret_cast<float4*>(out + (size_t)row * OUT_C + 4 * cq) = o;
}

// ---------------- launch ------------------------------------------------------
extern "C" void kernel_launch(void* const* d_in, const int* in_sizes, int n_in,
                              void* d_out, int out_size)
{
    const float* x  = (const float*)d_in[0];
    const int*   ei = (const int*)  d_in[1];
    const float* W1 = (const float*)d_in[2];
    const float* b1 = (const float*)d_in[3];
    const float* W2 = (const float*)d_in[4];
    const float* b2 = (const float*)d_in[5];
    float* out = (float*)d_out;

    const int* srcp = ei;             // edge_index[0]
    const int* dstp = ei + N_EDGES;   // edge_index[1]

    float *h1, *agg1, *x2, *h2, *agg2;
    cudaGetSymbolAddress((void**)&h1,   g_h1);
    cudaGetSymbolAddress((void**)&agg1, g_agg1);
    cudaGetSymbolAddress((void**)&x2,   g_x2);
    cudaGetSymbolAddress((void**)&h2,   g_h2);
    cudaGetSymbolAddress((void**)&agg2, g_agg2);

    // degree + dinv
    k_deg_init <<<(N_NODES + 255) / 256, 256>>>();
    k_deg_count<<<(N_EDGES + 255) / 256, 256>>>(dstp);
    k_dinv     <<<(N_NODES + 255) / 256, 256>>>();

    const int gemm_blocks = (N_NODES + 63) / 64;

    // ---- layer 1 ----
    k_gemm_scale<HID_C><<<gemm_blocks, 256>>>(x, W1, h1, agg1);
    {
        long long t = (long long)N_EDGES * (HID_C / 4);
        k_scatter<HID_C><<<(int)((t + 255) / 256), 256>>>(srcp, dstp, h1, agg1);
    }
    k_epi1<<<(N_NODES * (HID_C / 4) + 255) / 256, 256>>>(b1);

    // ---- layer 2 ----
    k_gemm_scale<OUT_C><<<gemm_blocks, 256>>>(x2, W2, h2, agg2);
    {
        long long t = (long long)N_EDGES * (OUT_C / 4);
        k_scatter<OUT_C><<<(int)((t + 255) / 256), 256>>>(srcp, dstp, h2, agg2);
    }
    k_epi2<<<(N_NODES * (OUT_C / 4) + 255) / 256, 256>>>(b2, out);
}